// round 9
// baseline (speedup 1.0000x reference)
#include <cuda_runtime.h>
#include <math.h>

#define NB 4
#define CH 64
#define HH 256
#define WW 448
#define HW (HH * WW)
#define NHW (NB * HW)
#define STRIDE 68   // 64 img channels + 1 metric + 3 pad (16B-aligned records)

// Scratch accumulator, NHWC layout: record of STRIDE floats per pixel.
__device__ float g_acc[(size_t)NHW * STRIDE];

// ---------------------------------------------------------------------------
// Kernel 1: zero the accumulator (float4 stores)
// ---------------------------------------------------------------------------
__global__ void zero_kernel() {
    size_t i = (size_t)blockIdx.x * blockDim.x + threadIdx.x;
    const size_t n4 = (size_t)NHW * STRIDE / 4;
    float4* p = reinterpret_cast<float4*>(g_acc);
    if (i < n4) p[i] = make_float4(0.f, 0.f, 0.f, 0.f);
}

// ---------------------------------------------------------------------------
// Kernel 2: splat. grid = (ceil(NHW/256), 17). blockIdx.y = channel quad q.
// q in [0,16): img channels 4q..4q+3 (scaled by exp(z)); q==16: metric quad.
// One red.global.add.v4.f32 per (pixel, quad, corner).
// ---------------------------------------------------------------------------
__global__ void splat_kernel(const float* __restrict__ img,
                             const float* __restrict__ flow,
                             const float* __restrict__ z) {
    int p = blockIdx.x * blockDim.x + threadIdx.x;
    if (p >= NHW) return;
    int q = blockIdx.y;

    int n   = p / HW;
    int rem = p - n * HW;
    int y   = rem / WW;
    int x   = rem - y * WW;

    float fx = (float)x + flow[(size_t)(n * 2 + 0) * HW + rem];
    float fy = (float)y + flow[(size_t)(n * 2 + 1) * HW + rem];
    bool finite = isfinite(fx) && isfinite(fy);
    float sx = finite ? fx : 0.f;
    float sy = finite ? fy : 0.f;

    float x0f = floorf(sx);
    float y0f = floorf(sy);
    int x0 = (int)x0f;
    int y0 = (int)y0f;
    float ax = sx - x0f;          // in [0,1)
    float ay = sy - y0f;

    float w00 = (1.f - ax) * (1.f - ay);
    float w10 = ax * (1.f - ay);
    float w01 = (1.f - ax) * ay;
    float w11 = ax * ay;

    bool inx0 = (x0 >= 0)     && (x0 < WW);
    bool inx1 = (x0 + 1 >= 0) && (x0 + 1 < WW);
    bool iny0 = (y0 >= 0)     && (y0 < HH);
    bool iny1 = (y0 + 1 >= 0) && (y0 + 1 < HH);

    float metric = __expf(z[(size_t)n * HW + rem]);

    float4 v;
    if (q < 16) {
        int c0 = q * 4;
        const float* ip = img + ((size_t)(n * CH + c0)) * HW + rem;
        v.x = ip[0]        * metric;
        v.y = ip[HW]       * metric;
        v.z = ip[2 * (size_t)HW] * metric;
        v.w = ip[3 * (size_t)HW] * metric;
    } else {
        v = make_float4(metric, 0.f, 0.f, 0.f);
    }

    if (!finite) return;

    size_t nbase = (size_t)n * HW;
    int    coff  = 4 * q;

#define DO_ADD(TY, TX, W)                                                     \
    do {                                                                      \
        float* dst = g_acc + (nbase + (size_t)(TY) * WW + (TX)) * STRIDE + coff; \
        unsigned long long ga = __cvta_generic_to_global(dst);                \
        float a0 = v.x * (W), a1 = v.y * (W), a2 = v.z * (W), a3 = v.w * (W); \
        asm volatile("red.global.add.v4.f32 [%0], {%1, %2, %3, %4};"          \
                     :: "l"(ga), "f"(a0), "f"(a1), "f"(a2), "f"(a3)           \
                     : "memory");                                             \
    } while (0)

    if (inx0 && iny0) DO_ADD(y0,     x0,     w00);
    if (inx1 && iny0) DO_ADD(y0,     x0 + 1, w10);
    if (inx0 && iny1) DO_ADD(y0 + 1, x0,     w01);
    if (inx1 && iny1) DO_ADD(y0 + 1, x0 + 1, w11);
#undef DO_ADD
}

// ---------------------------------------------------------------------------
// Kernel 3: normalize + transpose NHWC -> NCHW.
// Block = 256 threads = 32 consecutive pixels (same row, W%32==0) x 8 warps.
// Each warp handles channel lanes c = co*8 + (tid/32) over an 8-iter loop.
// NHWC records stay hot in L1; NCHW writes are coalesced.
// ---------------------------------------------------------------------------
__global__ void norm_kernel(float* __restrict__ out) {
    int pix0 = blockIdx.x * 32;
    int xi = threadIdx.x & 31;
    int cg = threadIdx.x >> 5;          // 0..7
    int p = pix0 + xi;

    int n   = p / HW;
    int rem = p - n * HW;

    const float* rec = g_acc + (size_t)p * STRIDE;
    float nrm = rec[64];
    if (nrm == 0.f) nrm = 1.f;
    float rn = 1.f / nrm;

#pragma unroll
    for (int co = 0; co < 8; co++) {
        int c = co * 8 + cg;
        out[((size_t)(n * CH + c)) * HW + rem] = rec[c] * rn;
    }
}

// ---------------------------------------------------------------------------
extern "C" void kernel_launch(void* const* d_in, const int* in_sizes, int n_in,
                              void* d_out, int out_size) {
    const float* img  = (const float*)d_in[0];
    const float* flow = (const float*)d_in[1];
    const float* z    = (const float*)d_in[2];
    float* out = (float*)d_out;

    // 1) zero accumulator
    {
        size_t n4 = (size_t)NHW * STRIDE / 4;
        int grid = (int)((n4 + 255) / 256);
        zero_kernel<<<grid, 256>>>();
    }
    // 2) splat
    {
        dim3 grid((NHW + 255) / 256, 17);
        splat_kernel<<<grid, 256>>>(img, flow, z);
    }
    // 3) normalize + layout transform
    {
        int grid = NHW / 32;
        norm_kernel<<<grid, 256>>>(out);
    }
}

// round 10
// speedup vs baseline: 1.0079x; 1.0079x over previous
#include <cuda_runtime.h>
#include <math.h>

#define NB 4
#define CH 64
#define HH 256
#define WW 448
#define HW (HH * WW)
#define NHW (NB * HW)
#define STRIDE 68   // 64 img channels + 1 metric + 3 pad (16B-aligned records)

// Scratch accumulator, NHWC layout: record of STRIDE floats per pixel.
__device__ float g_acc[(size_t)NHW * STRIDE];

// ---------------------------------------------------------------------------
// Kernel 1: zero the accumulator (float4 stores)
// ---------------------------------------------------------------------------
__global__ void zero_kernel() {
    size_t i = (size_t)blockIdx.x * blockDim.x + threadIdx.x;
    const size_t n4 = (size_t)NHW * STRIDE / 4;
    float4* p = reinterpret_cast<float4*>(g_acc);
    if (i < n4) p[i] = make_float4(0.f, 0.f, 0.f, 0.f);
}

// ---------------------------------------------------------------------------
// Kernel 2: splat. grid = (ceil(NHW/256), 17). blockIdx.y = channel quad q.
// q in [0,16): img channels 4q..4q+3 (scaled by exp(z)); q==16: metric quad.
// One red.global.add.v4.f32 per (pixel, quad, corner).
// ---------------------------------------------------------------------------
__global__ void splat_kernel(const float* __restrict__ img,
                             const float* __restrict__ flow,
                             const float* __restrict__ z) {
    int p = blockIdx.x * blockDim.x + threadIdx.x;
    if (p >= NHW) return;
    int q = blockIdx.y;

    int n   = p / HW;
    int rem = p - n * HW;
    int y   = rem / WW;
    int x   = rem - y * WW;

    float fx = (float)x + flow[(size_t)(n * 2 + 0) * HW + rem];
    float fy = (float)y + flow[(size_t)(n * 2 + 1) * HW + rem];
    bool finite = isfinite(fx) && isfinite(fy);
    float sx = finite ? fx : 0.f;
    float sy = finite ? fy : 0.f;

    float x0f = floorf(sx);
    float y0f = floorf(sy);
    int x0 = (int)x0f;
    int y0 = (int)y0f;
    float ax = sx - x0f;          // in [0,1)
    float ay = sy - y0f;

    float w00 = (1.f - ax) * (1.f - ay);
    float w10 = ax * (1.f - ay);
    float w01 = (1.f - ax) * ay;
    float w11 = ax * ay;

    bool inx0 = (x0 >= 0)     && (x0 < WW);
    bool inx1 = (x0 + 1 >= 0) && (x0 + 1 < WW);
    bool iny0 = (y0 >= 0)     && (y0 < HH);
    bool iny1 = (y0 + 1 >= 0) && (y0 + 1 < HH);

    float metric = __expf(z[(size_t)n * HW + rem]);

    float4 v;
    if (q < 16) {
        int c0 = q * 4;
        const float* ip = img + ((size_t)(n * CH + c0)) * HW + rem;
        v.x = ip[0]        * metric;
        v.y = ip[HW]       * metric;
        v.z = ip[2 * (size_t)HW] * metric;
        v.w = ip[3 * (size_t)HW] * metric;
    } else {
        v = make_float4(metric, 0.f, 0.f, 0.f);
    }

    if (!finite) return;

    size_t nbase = (size_t)n * HW;
    int    coff  = 4 * q;

#define DO_ADD(TY, TX, W)                                                     \
    do {                                                                      \
        float* dst = g_acc + (nbase + (size_t)(TY) * WW + (TX)) * STRIDE + coff; \
        unsigned long long ga = __cvta_generic_to_global(dst);                \
        float a0 = v.x * (W), a1 = v.y * (W), a2 = v.z * (W), a3 = v.w * (W); \
        asm volatile("red.global.add.v4.f32 [%0], {%1, %2, %3, %4};"          \
                     :: "l"(ga), "f"(a0), "f"(a1), "f"(a2), "f"(a3)           \
                     : "memory");                                             \
    } while (0)

    if (inx0 && iny0) DO_ADD(y0,     x0,     w00);
    if (inx1 && iny0) DO_ADD(y0,     x0 + 1, w10);
    if (inx0 && iny1) DO_ADD(y0 + 1, x0,     w01);
    if (inx1 && iny1) DO_ADD(y0 + 1, x0 + 1, w11);
#undef DO_ADD
}

// ---------------------------------------------------------------------------
// Kernel 3: normalize + transpose NHWC -> NCHW.
// Block = 256 threads = 32 consecutive pixels (same row, W%32==0) x 8 warps.
// Each warp handles channel lanes c = co*8 + (tid/32) over an 8-iter loop.
// NHWC records stay hot in L1; NCHW writes are coalesced.
// ---------------------------------------------------------------------------
__global__ void norm_kernel(float* __restrict__ out) {
    int pix0 = blockIdx.x * 32;
    int xi = threadIdx.x & 31;
    int cg = threadIdx.x >> 5;          // 0..7
    int p = pix0 + xi;

    int n   = p / HW;
    int rem = p - n * HW;

    const float* rec = g_acc + (size_t)p * STRIDE;
    float nrm = rec[64];
    if (nrm == 0.f) nrm = 1.f;
    float rn = 1.f / nrm;

#pragma unroll
    for (int co = 0; co < 8; co++) {
        int c = co * 8 + cg;
        out[((size_t)(n * CH + c)) * HW + rem] = rec[c] * rn;
    }
}

// ---------------------------------------------------------------------------
extern "C" void kernel_launch(void* const* d_in, const int* in_sizes, int n_in,
                              void* d_out, int out_size) {
    const float* img  = (const float*)d_in[0];
    const float* flow = (const float*)d_in[1];
    const float* z    = (const float*)d_in[2];
    float* out = (float*)d_out;

    // 1) zero accumulator
    {
        size_t n4 = (size_t)NHW * STRIDE / 4;
        int grid = (int)((n4 + 255) / 256);
        zero_kernel<<<grid, 256>>>();
    }
    // 2) splat
    {
        dim3 grid((NHW + 255) / 256, 17);
        splat_kernel<<<grid, 256>>>(img, flow, z);
    }
    // 3) normalize + layout transform
    {
        int grid = NHW / 32;
        norm_kernel<<<grid, 256>>>(out);
    }
}

// round 11
// speedup vs baseline: 1.0086x; 1.0007x over previous
#include <cuda_runtime.h>
#include <math.h>

#define NB 4
#define CH 64
#define HH 256
#define WW 448
#define HW (HH * WW)
#define NHW (NB * HW)
#define STRIDE 68   // 64 img channels + 1 metric + 3 pad (16B-aligned records)

// Scratch accumulator, NHWC layout: record of STRIDE floats per pixel.
__device__ float g_acc[(size_t)NHW * STRIDE];

// ---------------------------------------------------------------------------
// Kernel 1: zero the accumulator (float4 stores)
// ---------------------------------------------------------------------------
__global__ void zero_kernel() {
    size_t i = (size_t)blockIdx.x * blockDim.x + threadIdx.x;
    const size_t n4 = (size_t)NHW * STRIDE / 4;
    float4* p = reinterpret_cast<float4*>(g_acc);
    if (i < n4) p[i] = make_float4(0.f, 0.f, 0.f, 0.f);
}

// ---------------------------------------------------------------------------
// Kernel 2: splat. grid = (ceil(NHW/256), 17). blockIdx.y = channel quad q.
// q in [0,16): img channels 4q..4q+3 (scaled by exp(z)); q==16: metric quad.
// One red.global.add.v4.f32 per (pixel, quad, corner).
// ---------------------------------------------------------------------------
__global__ void splat_kernel(const float* __restrict__ img,
                             const float* __restrict__ flow,
                             const float* __restrict__ z) {
    int p = blockIdx.x * blockDim.x + threadIdx.x;
    if (p >= NHW) return;
    int q = blockIdx.y;

    int n   = p / HW;
    int rem = p - n * HW;
    int y   = rem / WW;
    int x   = rem - y * WW;

    float fx = (float)x + flow[(size_t)(n * 2 + 0) * HW + rem];
    float fy = (float)y + flow[(size_t)(n * 2 + 1) * HW + rem];
    bool finite = isfinite(fx) && isfinite(fy);
    float sx = finite ? fx : 0.f;
    float sy = finite ? fy : 0.f;

    float x0f = floorf(sx);
    float y0f = floorf(sy);
    int x0 = (int)x0f;
    int y0 = (int)y0f;
    float ax = sx - x0f;          // in [0,1)
    float ay = sy - y0f;

    float w00 = (1.f - ax) * (1.f - ay);
    float w10 = ax * (1.f - ay);
    float w01 = (1.f - ax) * ay;
    float w11 = ax * ay;

    bool inx0 = (x0 >= 0)     && (x0 < WW);
    bool inx1 = (x0 + 1 >= 0) && (x0 + 1 < WW);
    bool iny0 = (y0 >= 0)     && (y0 < HH);
    bool iny1 = (y0 + 1 >= 0) && (y0 + 1 < HH);

    float metric = __expf(z[(size_t)n * HW + rem]);

    float4 v;
    if (q < 16) {
        int c0 = q * 4;
        const float* ip = img + ((size_t)(n * CH + c0)) * HW + rem;
        v.x = ip[0]        * metric;
        v.y = ip[HW]       * metric;
        v.z = ip[2 * (size_t)HW] * metric;
        v.w = ip[3 * (size_t)HW] * metric;
    } else {
        v = make_float4(metric, 0.f, 0.f, 0.f);
    }

    if (!finite) return;

    size_t nbase = (size_t)n * HW;
    int    coff  = 4 * q;

#define DO_ADD(TY, TX, W)                                                     \
    do {                                                                      \
        float* dst = g_acc + (nbase + (size_t)(TY) * WW + (TX)) * STRIDE + coff; \
        unsigned long long ga = __cvta_generic_to_global(dst);                \
        float a0 = v.x * (W), a1 = v.y * (W), a2 = v.z * (W), a3 = v.w * (W); \
        asm volatile("red.global.add.v4.f32 [%0], {%1, %2, %3, %4};"          \
                     :: "l"(ga), "f"(a0), "f"(a1), "f"(a2), "f"(a3)           \
                     : "memory");                                             \
    } while (0)

    if (inx0 && iny0) DO_ADD(y0,     x0,     w00);
    if (inx1 && iny0) DO_ADD(y0,     x0 + 1, w10);
    if (inx0 && iny1) DO_ADD(y0 + 1, x0,     w01);
    if (inx1 && iny1) DO_ADD(y0 + 1, x0 + 1, w11);
#undef DO_ADD
}

// ---------------------------------------------------------------------------
// Kernel 3: normalize + transpose NHWC -> NCHW.
// Block = 256 threads = 32 consecutive pixels (same row, W%32==0) x 8 warps.
// Each warp handles channel lanes c = co*8 + (tid/32) over an 8-iter loop.
// NHWC records stay hot in L1; NCHW writes are coalesced.
// ---------------------------------------------------------------------------
__global__ void norm_kernel(float* __restrict__ out) {
    int pix0 = blockIdx.x * 32;
    int xi = threadIdx.x & 31;
    int cg = threadIdx.x >> 5;          // 0..7
    int p = pix0 + xi;

    int n   = p / HW;
    int rem = p - n * HW;

    const float* rec = g_acc + (size_t)p * STRIDE;
    float nrm = rec[64];
    if (nrm == 0.f) nrm = 1.f;
    float rn = 1.f / nrm;

#pragma unroll
    for (int co = 0; co < 8; co++) {
        int c = co * 8 + cg;
        out[((size_t)(n * CH + c)) * HW + rem] = rec[c] * rn;
    }
}

// ---------------------------------------------------------------------------
extern "C" void kernel_launch(void* const* d_in, const int* in_sizes, int n_in,
                              void* d_out, int out_size) {
    const float* img  = (const float*)d_in[0];
    const float* flow = (const float*)d_in[1];
    const float* z    = (const float*)d_in[2];
    float* out = (float*)d_out;

    // 1) zero accumulator
    {
        size_t n4 = (size_t)NHW * STRIDE / 4;
        int grid = (int)((n4 + 255) / 256);
        zero_kernel<<<grid, 256>>>();
    }
    // 2) splat
    {
        dim3 grid((NHW + 255) / 256, 17);
        splat_kernel<<<grid, 256>>>(img, flow, z);
    }
    // 3) normalize + layout transform
    {
        int grid = NHW / 32;
        norm_kernel<<<grid, 256>>>(out);
    }
}

// round 12
// speedup vs baseline: 1.0096x; 1.0010x over previous
#include <cuda_runtime.h>
#include <math.h>

#define NB 4
#define CH 64
#define HH 256
#define WW 448
#define HW (HH * WW)
#define NHW (NB * HW)
#define STRIDE 68   // 64 img channels + 1 metric + 3 pad (16B-aligned records)

// Scratch accumulator, NHWC layout: record of STRIDE floats per pixel.
__device__ float g_acc[(size_t)NHW * STRIDE];

// ---------------------------------------------------------------------------
// Kernel 1: zero the accumulator (float4 stores)
// ---------------------------------------------------------------------------
__global__ void zero_kernel() {
    size_t i = (size_t)blockIdx.x * blockDim.x + threadIdx.x;
    const size_t n4 = (size_t)NHW * STRIDE / 4;
    float4* p = reinterpret_cast<float4*>(g_acc);
    if (i < n4) p[i] = make_float4(0.f, 0.f, 0.f, 0.f);
}

// ---------------------------------------------------------------------------
// Kernel 2: splat. grid = (ceil(NHW/256), 17). blockIdx.y = channel quad q.
// q in [0,16): img channels 4q..4q+3 (scaled by exp(z)); q==16: metric quad.
// One red.global.add.v4.f32 per (pixel, quad, corner).
// ---------------------------------------------------------------------------
__global__ void splat_kernel(const float* __restrict__ img,
                             const float* __restrict__ flow,
                             const float* __restrict__ z) {
    int p = blockIdx.x * blockDim.x + threadIdx.x;
    if (p >= NHW) return;
    int q = blockIdx.y;

    int n   = p / HW;
    int rem = p - n * HW;
    int y   = rem / WW;
    int x   = rem - y * WW;

    float fx = (float)x + flow[(size_t)(n * 2 + 0) * HW + rem];
    float fy = (float)y + flow[(size_t)(n * 2 + 1) * HW + rem];
    bool finite = isfinite(fx) && isfinite(fy);
    float sx = finite ? fx : 0.f;
    float sy = finite ? fy : 0.f;

    float x0f = floorf(sx);
    float y0f = floorf(sy);
    int x0 = (int)x0f;
    int y0 = (int)y0f;
    float ax = sx - x0f;          // in [0,1)
    float ay = sy - y0f;

    float w00 = (1.f - ax) * (1.f - ay);
    float w10 = ax * (1.f - ay);
    float w01 = (1.f - ax) * ay;
    float w11 = ax * ay;

    bool inx0 = (x0 >= 0)     && (x0 < WW);
    bool inx1 = (x0 + 1 >= 0) && (x0 + 1 < WW);
    bool iny0 = (y0 >= 0)     && (y0 < HH);
    bool iny1 = (y0 + 1 >= 0) && (y0 + 1 < HH);

    float metric = __expf(z[(size_t)n * HW + rem]);

    float4 v;
    if (q < 16) {
        int c0 = q * 4;
        const float* ip = img + ((size_t)(n * CH + c0)) * HW + rem;
        v.x = ip[0]        * metric;
        v.y = ip[HW]       * metric;
        v.z = ip[2 * (size_t)HW] * metric;
        v.w = ip[3 * (size_t)HW] * metric;
    } else {
        v = make_float4(metric, 0.f, 0.f, 0.f);
    }

    if (!finite) return;

    size_t nbase = (size_t)n * HW;
    int    coff  = 4 * q;

#define DO_ADD(TY, TX, W)                                                     \
    do {                                                                      \
        float* dst = g_acc + (nbase + (size_t)(TY) * WW + (TX)) * STRIDE + coff; \
        unsigned long long ga = __cvta_generic_to_global(dst);                \
        float a0 = v.x * (W), a1 = v.y * (W), a2 = v.z * (W), a3 = v.w * (W); \
        asm volatile("red.global.add.v4.f32 [%0], {%1, %2, %3, %4};"          \
                     :: "l"(ga), "f"(a0), "f"(a1), "f"(a2), "f"(a3)           \
                     : "memory");                                             \
    } while (0)

    if (inx0 && iny0) DO_ADD(y0,     x0,     w00);
    if (inx1 && iny0) DO_ADD(y0,     x0 + 1, w10);
    if (inx0 && iny1) DO_ADD(y0 + 1, x0,     w01);
    if (inx1 && iny1) DO_ADD(y0 + 1, x0 + 1, w11);
#undef DO_ADD
}

// ---------------------------------------------------------------------------
// Kernel 3: normalize + transpose NHWC -> NCHW.
// Block = 256 threads = 32 consecutive pixels (same row, W%32==0) x 8 warps.
// Each warp handles channel lanes c = co*8 + (tid/32) over an 8-iter loop.
// NHWC records stay hot in L1; NCHW writes are coalesced.
// ---------------------------------------------------------------------------
__global__ void norm_kernel(float* __restrict__ out) {
    int pix0 = blockIdx.x * 32;
    int xi = threadIdx.x & 31;
    int cg = threadIdx.x >> 5;          // 0..7
    int p = pix0 + xi;

    int n   = p / HW;
    int rem = p - n * HW;

    const float* rec = g_acc + (size_t)p * STRIDE;
    float nrm = rec[64];
    if (nrm == 0.f) nrm = 1.f;
    float rn = 1.f / nrm;

#pragma unroll
    for (int co = 0; co < 8; co++) {
        int c = co * 8 + cg;
        out[((size_t)(n * CH + c)) * HW + rem] = rec[c] * rn;
    }
}

// ---------------------------------------------------------------------------
extern "C" void kernel_launch(void* const* d_in, const int* in_sizes, int n_in,
                              void* d_out, int out_size) {
    const float* img  = (const float*)d_in[0];
    const float* flow = (const float*)d_in[1];
    const float* z    = (const float*)d_in[2];
    float* out = (float*)d_out;

    // 1) zero accumulator
    {
        size_t n4 = (size_t)NHW * STRIDE / 4;
        int grid = (int)((n4 + 255) / 256);
        zero_kernel<<<grid, 256>>>();
    }
    // 2) splat
    {
        dim3 grid((NHW + 255) / 256, 17);
        splat_kernel<<<grid, 256>>>(img, flow, z);
    }
    // 3) normalize + layout transform
    {
        int grid = NHW / 32;
        norm_kernel<<<grid, 256>>>(out);
    }
}

// round 13
// speedup vs baseline: 1.0108x; 1.0011x over previous
#include <cuda_runtime.h>
#include <math.h>

#define NB 4
#define CH 64
#define HH 256
#define WW 448
#define HW (HH * WW)
#define NHW (NB * HW)
#define STRIDE 68   // 64 img channels + 1 metric + 3 pad (16B-aligned records)

// Scratch accumulator, NHWC layout: record of STRIDE floats per pixel.
__device__ float g_acc[(size_t)NHW * STRIDE];

// ---------------------------------------------------------------------------
// Kernel 1: zero the accumulator (float4 stores)
// ---------------------------------------------------------------------------
__global__ void zero_kernel() {
    size_t i = (size_t)blockIdx.x * blockDim.x + threadIdx.x;
    const size_t n4 = (size_t)NHW * STRIDE / 4;
    float4* p = reinterpret_cast<float4*>(g_acc);
    if (i < n4) p[i] = make_float4(0.f, 0.f, 0.f, 0.f);
}

// ---------------------------------------------------------------------------
// Kernel 2: splat. grid = (ceil(NHW/256), 17). blockIdx.y = channel quad q.
// q in [0,16): img channels 4q..4q+3 (scaled by exp(z)); q==16: metric quad.
// One red.global.add.v4.f32 per (pixel, quad, corner).
// ---------------------------------------------------------------------------
__global__ void splat_kernel(const float* __restrict__ img,
                             const float* __restrict__ flow,
                             const float* __restrict__ z) {
    int p = blockIdx.x * blockDim.x + threadIdx.x;
    if (p >= NHW) return;
    int q = blockIdx.y;

    int n   = p / HW;
    int rem = p - n * HW;
    int y   = rem / WW;
    int x   = rem - y * WW;

    float fx = (float)x + flow[(size_t)(n * 2 + 0) * HW + rem];
    float fy = (float)y + flow[(size_t)(n * 2 + 1) * HW + rem];
    bool finite = isfinite(fx) && isfinite(fy);
    float sx = finite ? fx : 0.f;
    float sy = finite ? fy : 0.f;

    float x0f = floorf(sx);
    float y0f = floorf(sy);
    int x0 = (int)x0f;
    int y0 = (int)y0f;
    float ax = sx - x0f;          // in [0,1)
    float ay = sy - y0f;

    float w00 = (1.f - ax) * (1.f - ay);
    float w10 = ax * (1.f - ay);
    float w01 = (1.f - ax) * ay;
    float w11 = ax * ay;

    bool inx0 = (x0 >= 0)     && (x0 < WW);
    bool inx1 = (x0 + 1 >= 0) && (x0 + 1 < WW);
    bool iny0 = (y0 >= 0)     && (y0 < HH);
    bool iny1 = (y0 + 1 >= 0) && (y0 + 1 < HH);

    float metric = __expf(z[(size_t)n * HW + rem]);

    float4 v;
    if (q < 16) {
        int c0 = q * 4;
        const float* ip = img + ((size_t)(n * CH + c0)) * HW + rem;
        v.x = ip[0]        * metric;
        v.y = ip[HW]       * metric;
        v.z = ip[2 * (size_t)HW] * metric;
        v.w = ip[3 * (size_t)HW] * metric;
    } else {
        v = make_float4(metric, 0.f, 0.f, 0.f);
    }

    if (!finite) return;

    size_t nbase = (size_t)n * HW;
    int    coff  = 4 * q;

#define DO_ADD(TY, TX, W)                                                     \
    do {                                                                      \
        float* dst = g_acc + (nbase + (size_t)(TY) * WW + (TX)) * STRIDE + coff; \
        unsigned long long ga = __cvta_generic_to_global(dst);                \
        float a0 = v.x * (W), a1 = v.y * (W), a2 = v.z * (W), a3 = v.w * (W); \
        asm volatile("red.global.add.v4.f32 [%0], {%1, %2, %3, %4};"          \
                     :: "l"(ga), "f"(a0), "f"(a1), "f"(a2), "f"(a3)           \
                     : "memory");                                             \
    } while (0)

    if (inx0 && iny0) DO_ADD(y0,     x0,     w00);
    if (inx1 && iny0) DO_ADD(y0,     x0 + 1, w10);
    if (inx0 && iny1) DO_ADD(y0 + 1, x0,     w01);
    if (inx1 && iny1) DO_ADD(y0 + 1, x0 + 1, w11);
#undef DO_ADD
}

// ---------------------------------------------------------------------------
// Kernel 3: normalize + transpose NHWC -> NCHW.
// Block = 256 threads = 32 consecutive pixels (same row, W%32==0) x 8 warps.
// Each warp handles channel lanes c = co*8 + (tid/32) over an 8-iter loop.
// NHWC records stay hot in L1; NCHW writes are coalesced.
// ---------------------------------------------------------------------------
__global__ void norm_kernel(float* __restrict__ out) {
    int pix0 = blockIdx.x * 32;
    int xi = threadIdx.x & 31;
    int cg = threadIdx.x >> 5;          // 0..7
    int p = pix0 + xi;

    int n   = p / HW;
    int rem = p - n * HW;

    const float* rec = g_acc + (size_t)p * STRIDE;
    float nrm = rec[64];
    if (nrm == 0.f) nrm = 1.f;
    float rn = 1.f / nrm;

#pragma unroll
    for (int co = 0; co < 8; co++) {
        int c = co * 8 + cg;
        out[((size_t)(n * CH + c)) * HW + rem] = rec[c] * rn;
    }
}

// ---------------------------------------------------------------------------
extern "C" void kernel_launch(void* const* d_in, const int* in_sizes, int n_in,
                              void* d_out, int out_size) {
    const float* img  = (const float*)d_in[0];
    const float* flow = (const float*)d_in[1];
    const float* z    = (const float*)d_in[2];
    float* out = (float*)d_out;

    // 1) zero accumulator
    {
        size_t n4 = (size_t)NHW * STRIDE / 4;
        int grid = (int)((n4 + 255) / 256);
        zero_kernel<<<grid, 256>>>();
    }
    // 2) splat
    {
        dim3 grid((NHW + 255) / 256, 17);
        splat_kernel<<<grid, 256>>>(img, flow, z);
    }
    // 3) normalize + layout transform
    {
        int grid = NHW / 32;
        norm_kernel<<<grid, 256>>>(out);
    }
}